// round 2
// baseline (speedup 1.0000x reference)
#include <cuda_runtime.h>
#include <math.h>

// Problem constants
#define S_N 16
#define B_N 128
#define T_N 200
#define L_N 64
#define R_N 16
#define H_N 256
#define NT  256
#define LP  65            // padded row stride for 64x64 matrices (conflict-free column reads)
#define TRI (L_N*(L_N+1)/2)   // 2080 lower-tri entries

// ---- shared memory layout (floats) ----
#define O_W1  0
#define O_W2  (O_W1 + L_N*H_N)        // 16384
#define O_B1  (O_W2 + H_N*L_N)        // +16384
#define O_B2  (O_B1 + H_N)
#define O_Z   (O_B2 + L_N)
#define O_HID (O_Z + S_N*L_N)
#define O_M   (O_HID + S_N*H_N)
#define O_A   (O_M + S_N*L_N)
#define O_BI  (O_A + L_N*LP)
#define O_JP  (O_BI + L_N*LP)
#define O_KT  (O_JP + L_N*LP)
#define O_WT  (O_KT + L_N*R_N)
#define O_MP  (O_WT + S_N*L_N)
#define O_HF  (O_MP + L_N)
#define O_MF  (O_HF + L_N)
#define O_U   (O_MF + L_N)
#define O_DG  (O_U + L_N)
#define O_QD  (O_DG + L_N)
#define O_J0  (O_QD + L_N)
#define O_M0  (O_J0 + L_N)
#define O_SP  (O_M0 + L_N)
#define SMF   (O_SP + L_N)            // total floats (= 54336 -> 217344 bytes)

// ---- output offsets (tuple flattened in order) ----
#define OFF_ZF 0LL
#define OFF_MFo ((long long)S_N*B_N*T_N*L_N)                  // 26,214,400
#define OFF_MPo (OFF_MFo + (long long)B_N*T_N*L_N)            // +1,638,400
#define OFF_PF  (OFF_MPo + (long long)B_N*T_N*L_N)
#define OFF_PP  (OFF_PF + (long long)B_N*T_N*L_N*L_N)

// map linear index e -> (i,j) with j<=i over the lower triangle
__device__ __forceinline__ void trimap(int e, int &i, int &j) {
    int ii = (int)((sqrtf(8.0f*(float)e + 1.0f) - 1.0f) * 0.5f);
    while ((ii+1)*(ii+2)/2 <= e) ++ii;
    while (ii*(ii+1)/2 > e) --ii;
    i = ii;
    j = e - ii*(ii+1)/2;
}

// In-place Cholesky of lower-triangular-stored A (stride LP).
// One barrier per column (LDL-style rank-1 updates with unscaled columns),
// then one parallel scaling pass. dg[j] = 1/L[j][j] on exit (needed by solver).
__device__ void chol_inplace(float* A, float* dg, int tid) {
    const int warp = tid >> 5, lane = tid & 31;
    #pragma unroll 1
    for (int j = 0; j < L_N - 1; ++j) {
        __syncthreads();
        const float inv = 1.0f / A[j*LP + j];
        #pragma unroll 1
        for (int i = j + 1 + warp; i < L_N; i += NT/32) {
            const float fac = A[i*LP + j] * inv;
            for (int kk = j + 1 + lane; kk <= i; kk += 32)
                A[i*LP + kk] -= fac * A[kk*LP + j];
        }
    }
    __syncthreads();
    if (tid < L_N) dg[tid] = rsqrtf(A[tid*LP + tid]);
    __syncthreads();
    for (int e = tid; e < TRI; e += NT) {
        int i, j; trimap(e, i, j);
        A[i*LP + j] *= dg[j];     // diag becomes sqrt(d_j); dg[j] stays = 1/L[j][j]
    }
    __syncthreads();
}

// X = inv(A) for lower-triangular A (reads lower part only, writes lower part of X).
// Row-sweep forward substitution, all 64 unit-vector RHS in parallel:
// 4 lanes per column split the dot product, shfl-reduced.
__device__ void tri_inverse(const float* A, float* X, const float* dg, int tid) {
    const int c = tid >> 2, r = tid & 3;
    #pragma unroll 1
    for (int i = 0; i < L_N; ++i) {
        __syncthreads();
        float sum = 0.0f;
        for (int j = c + r; j < i; j += 4)
            sum += A[i*LP + j] * X[j*LP + c];
        sum += __shfl_down_sync(0xffffffffu, sum, 1);
        sum += __shfl_down_sync(0xffffffffu, sum, 2);
        if (r == 0 && c <= i)
            X[i*LP + c] = (c == i) ? dg[i] : (-sum * dg[i]);
    }
    __syncthreads();
}

__global__ void __launch_bounds__(NT, 1)
nlf_kernel(const float* __restrict__ gk,  const float* __restrict__ gK,
           const float* __restrict__ glogQ, const float* __restrict__ gm0,
           const float* __restrict__ glogv0, const float* __restrict__ gW1,
           const float* __restrict__ gb1, const float* __restrict__ gW2,
           const float* __restrict__ gb2, const float* __restrict__ gw,
           float* __restrict__ out)
{
    extern __shared__ float sm[];
    const int tid = threadIdx.x;
    const int b   = blockIdx.x;

    // ---- one-time setup: weights + softplus-derived vectors ----
    {
        const float4* g1 = (const float4*)gW1;
        float4* s1 = (float4*)(sm + O_W1);
        for (int i = tid; i < L_N*H_N/4; i += NT) s1[i] = g1[i];
        const float4* g2 = (const float4*)gW2;
        float4* s2 = (float4*)(sm + O_W2);
        for (int i = tid; i < H_N*L_N/4; i += NT) s2[i] = g2[i];
        if (tid < H_N) sm[O_B1 + tid] = gb1[tid];
        if (tid < L_N) {
            sm[O_B2 + tid] = gb2[tid];
            float q = glogQ[tid], v = glogv0[tid];
            float qd = fmaxf(q, 0.f) + log1pf(expf(-fabsf(q)));   // softplus(log_Q)
            float p0 = fmaxf(v, 0.f) + log1pf(expf(-fabsf(v)));   // softplus(log_v0)
            sm[O_QD + tid] = qd;
            sm[O_J0 + tid] = 1.0f / p0;
            sm[O_SP + tid] = sqrtf(p0);
            sm[O_M0 + tid] = gm0[tid];
        }
    }
    __syncthreads();

    float* const sZ  = sm + O_Z;
    float* const sHID= sm + O_HID;
    float* const sM  = sm + O_M;
    float* const sA  = sm + O_A;
    float* const sBI = sm + O_BI;
    float* const sJP = sm + O_JP;
    float* const sKT = sm + O_KT;
    float* const sWT = sm + O_WT;
    float* const sMP = sm + O_MP;
    float* const sHF = sm + O_HF;
    float* const sMF = sm + O_MF;
    float* const sU  = sm + O_U;
    float* const sDG = sm + O_DG;

    #pragma unroll 1
    for (int t = 0; t < T_N; ++t) {
        // ---- stage K_t (64x16) and w_t (16x64) early (prefetch-ish) ----
        {
            const float4* gkt = (const float4*)(gK + ((long long)(b*T_N + t))*L_N*R_N);
            float4* s4 = (float4*)sKT;
            for (int i = tid; i < L_N*R_N/4; i += NT) s4[i] = gkt[i];
            // w[t][s][b][:]: per-sample rows are strided by B*L floats
            const int ss = tid >> 4;            // 16 samples
            const int l4 = (tid & 15) * 4;      // 16 float4 per sample row
            const float4 wv = *(const float4*)(gw + (((long long)t*S_N + ss)*B_N + b)*L_N + l4);
            *(float4*)(sWT + ss*L_N + l4) = wv;
        }
        __syncthreads();

        if (t == 0) {
            if (tid < L_N) {
                sMP[tid] = sm[O_M0 + tid];
                sHF[tid] = sm[O_J0 + tid]*sm[O_M0 + tid] + gk[((long long)(b*T_N))*L_N + tid];
            }
            // P_p_chol[t=0] = diag(sqrt(P0))
            {
                float* po = out + OFF_PP + ((long long)(b*T_N + t))*L_N*L_N;
                for (int e = tid; e < L_N*L_N; e += NT) {
                    int i = e >> 6, j = e & 63;
                    po[e] = (i == j) ? sm[O_SP + i] : 0.0f;
                }
            }
            // J_f = diag(J0) + K0 K0^T (lower only)
            for (int e = tid; e < TRI; e += NT) {
                int i, j; trimap(e, i, j);
                float s = 0.f;
                #pragma unroll
                for (int rr = 0; rr < R_N; rr += 4) {
                    float4 a  = *(const float4*)(sKT + i*R_N + rr);
                    float4 bb = *(const float4*)(sKT + j*R_N + rr);
                    s += a.x*bb.x + a.y*bb.y + a.z*bb.z + a.w*bb.w;
                }
                if (i == j) s += sm[O_J0 + i];
                sA[i*LP + j] = s;
            }
        } else {
            // ---- MLP layer 1: hid = tanh(z @ W1 + b1), one h per thread ----
            {
                const int h = tid;
                float acc[S_N];
                const float bb1 = sm[O_B1 + h];
                #pragma unroll
                for (int s = 0; s < S_N; ++s) acc[s] = bb1;
                #pragma unroll 4
                for (int l = 0; l < L_N; l += 4) {
                    const float w0 = sm[O_W1 + (l+0)*H_N + h];
                    const float w1 = sm[O_W1 + (l+1)*H_N + h];
                    const float w2 = sm[O_W1 + (l+2)*H_N + h];
                    const float w3 = sm[O_W1 + (l+3)*H_N + h];
                    #pragma unroll
                    for (int s = 0; s < S_N; ++s) {
                        float4 z4 = *(const float4*)(sZ + s*L_N + l);
                        acc[s] += z4.x*w0 + z4.y*w1 + z4.z*w2 + z4.w*w3;
                    }
                }
                #pragma unroll
                for (int s = 0; s < S_N; ++s) sHID[s*H_N + h] = tanhf(acc[s]);
            }
            __syncthreads();
            // ---- MLP layer 2: m = hid @ W2 + b2, (4 samples, 1 column) per thread ----
            {
                const int lo = tid & 63;
                const int s0 = (tid >> 6) * 4;
                const float bb2 = sm[O_B2 + lo];
                float a0 = bb2, a1 = bb2, a2 = bb2, a3 = bb2;
                #pragma unroll 4
                for (int h = 0; h < H_N; h += 4) {
                    const float w0 = sm[O_W2 + (h+0)*L_N + lo];
                    const float w1 = sm[O_W2 + (h+1)*L_N + lo];
                    const float w2 = sm[O_W2 + (h+2)*L_N + lo];
                    const float w3 = sm[O_W2 + (h+3)*L_N + lo];
                    float4 h0 = *(const float4*)(sHID + (s0+0)*H_N + h);
                    float4 h1 = *(const float4*)(sHID + (s0+1)*H_N + h);
                    float4 h2 = *(const float4*)(sHID + (s0+2)*H_N + h);
                    float4 h3 = *(const float4*)(sHID + (s0+3)*H_N + h);
                    a0 += h0.x*w0 + h0.y*w1 + h0.z*w2 + h0.w*w3;
                    a1 += h1.x*w0 + h1.y*w1 + h1.z*w2 + h1.w*w3;
                    a2 += h2.x*w0 + h2.y*w1 + h2.z*w2 + h2.w*w3;
                    a3 += h3.x*w0 + h3.y*w1 + h3.z*w2 + h3.w*w3;
                }
                sM[(s0+0)*L_N + lo] = a0;
                sM[(s0+1)*L_N + lo] = a1;
                sM[(s0+2)*L_N + lo] = a2;
                sM[(s0+3)*L_N + lo] = a3;
            }
            __syncthreads();
            // ---- m_p = mean_s m ----
            if (tid < L_N) {
                float s = 0.f;
                #pragma unroll
                for (int ss = 0; ss < S_N; ++ss) s += sM[ss*L_N + tid];
                sMP[tid] = s * (1.0f/S_N);
            }
            __syncthreads();
            // ---- P_p = diag(Q) + Ezz/S - m_p m_p^T (lower only) ----
            for (int e = tid; e < TRI; e += NT) {
                int i, j; trimap(e, i, j);
                float s = 0.f;
                #pragma unroll
                for (int ss = 0; ss < S_N; ++ss) s += sM[ss*L_N + i]*sM[ss*L_N + j];
                float v = s * (1.0f/S_N) - sMP[i]*sMP[j];
                if (i == j) v += sm[O_QD + i];
                sA[i*LP + j] = v;
            }
            chol_inplace(sA, sDG, tid);          // sA = Lp
            // write P_p_chol
            {
                float* po = out + OFF_PP + ((long long)(b*T_N + t))*L_N*L_N;
                for (int e = tid; e < L_N*L_N; e += NT) {
                    int i = e >> 6, j = e & 63;
                    po[e] = (j <= i) ? sA[i*LP + j] : 0.0f;
                }
            }
            tri_inverse(sA, sBI, sDG, tid);      // sBI = Lp^{-1}
            // ---- J_p = BI^T BI (lower + mirror) ----
            for (int e = tid; e < TRI; e += NT) {
                int i, j; trimap(e, i, j);       // i >= j; sum k = i..63
                float s0 = 0.f, s1 = 0.f;
                int kk = i;
                for (; kk + 1 < L_N; kk += 2) {
                    s0 += sBI[(kk+0)*LP + i] * sBI[(kk+0)*LP + j];
                    s1 += sBI[(kk+1)*LP + i] * sBI[(kk+1)*LP + j];
                }
                if (kk < L_N) s0 += sBI[kk*LP + i] * sBI[kk*LP + j];
                const float s = s0 + s1;
                sJP[i*LP + j] = s;
                sJP[j*LP + i] = s;
            }
            __syncthreads();
            // ---- h_f = J_p m_p + k_t ----
            if (tid < L_N) {
                const float* row = sJP + tid*LP;
                float s0=0,s1=0,s2=0,s3=0;
                #pragma unroll
                for (int j = 0; j < L_N; j += 4) {
                    s0 += row[j+0]*sMP[j+0];
                    s1 += row[j+1]*sMP[j+1];
                    s2 += row[j+2]*sMP[j+2];
                    s3 += row[j+3]*sMP[j+3];
                }
                sHF[tid] = (s0+s1)+(s2+s3) + gk[((long long)(b*T_N + t))*L_N + tid];
            }
            __syncthreads();
            // ---- J_f = J_p + K_t K_t^T (lower only) ----
            for (int e = tid; e < TRI; e += NT) {
                int i, j; trimap(e, i, j);
                float s = 0.f;
                #pragma unroll
                for (int rr = 0; rr < R_N; rr += 4) {
                    float4 a  = *(const float4*)(sKT + i*R_N + rr);
                    float4 bb = *(const float4*)(sKT + j*R_N + rr);
                    s += a.x*bb.x + a.y*bb.y + a.z*bb.z + a.w*bb.w;
                }
                sA[i*LP + j] = sJP[i*LP + j] + s;
            }
        }

        // ================= common tail =================
        chol_inplace(sA, sDG, tid);        // sA = Lf (internal leading barrier orders the build)
        tri_inverse(sA, sBI, sDG, tid);    // sBI = Lf^{-1}

        // m_f = Lf^{-T} (Lf^{-1} h_f)
        if (tid < L_N) {
            const int i = tid;
            float s0 = 0.f, s1 = 0.f;
            int j = 0;
            for (; j + 1 <= i; j += 2) {
                s0 += sBI[i*LP + j]   * sHF[j];
                s1 += sBI[i*LP + j+1] * sHF[j+1];
            }
            if (j <= i) s0 += sBI[i*LP + j] * sHF[j];
            sU[i] = s0 + s1;
        }
        __syncthreads();
        if (tid < L_N) {
            const int i = tid;
            float s0 = 0.f, s1 = 0.f;
            int kk = i;
            for (; kk + 1 < L_N; kk += 2) {
                s0 += sBI[(kk+0)*LP + i] * sU[kk+0];
                s1 += sBI[(kk+1)*LP + i] * sU[kk+1];
            }
            if (kk < L_N) s0 += sBI[kk*LP + i] * sU[kk];
            sMF[i] = s0 + s1;
            out[OFF_MPo + ((long long)(b*T_N + t))*L_N + i] = sMP[i];
        }
        __syncthreads();
        if (tid < L_N)
            out[OFF_MFo + ((long long)(b*T_N + t))*L_N + tid] = sMF[tid];
        // P_f_chol = (Lf^{-1})^T  (upper triangular, zeros below)
        {
            float* po = out + OFF_PF + ((long long)(b*T_N + t))*L_N*L_N;
            for (int e = tid; e < L_N*L_N; e += NT) {
                int i = e >> 6, j = e & 63;
                po[e] = (j >= i) ? sBI[j*LP + i] : 0.0f;
            }
        }
        // z_f[s] = m_f + Pf_chol @ w_t[s]  (sum over j >= i of BI[j][i] * w[s][j])
        {
            const int i  = tid & 63;
            const int s0 = (tid >> 6) * 4;
            float z0 = sMF[i], z1 = z0, z2 = z0, z3 = z0;
            for (int j = i; j < L_N; ++j) {
                const float bv = sBI[j*LP + i];
                z0 += bv * sWT[(s0+0)*L_N + j];
                z1 += bv * sWT[(s0+1)*L_N + j];
                z2 += bv * sWT[(s0+2)*L_N + j];
                z3 += bv * sWT[(s0+3)*L_N + j];
            }
            sZ[(s0+0)*L_N + i] = z0;
            sZ[(s0+1)*L_N + i] = z1;
            sZ[(s0+2)*L_N + i] = z2;
            sZ[(s0+3)*L_N + i] = z3;
            out[((((long long)(s0+0))*B_N + b)*T_N + t)*L_N + i] = z0;
            out[((((long long)(s0+1))*B_N + b)*T_N + t)*L_N + i] = z1;
            out[((((long long)(s0+2))*B_N + b)*T_N + t)*L_N + i] = z2;
            out[((((long long)(s0+3))*B_N + b)*T_N + t)*L_N + i] = z3;
        }
        __syncthreads();   // sZ ready for next step's MLP; staging buffers free
    }
}

extern "C" void kernel_launch(void* const* d_in, const int* in_sizes, int n_in,
                              void* d_out, int out_size) {
    const float* gk     = (const float*)d_in[0];
    const float* gK     = (const float*)d_in[1];
    const float* glogQ  = (const float*)d_in[2];
    const float* gm0    = (const float*)d_in[3];
    const float* glogv0 = (const float*)d_in[4];
    const float* gW1    = (const float*)d_in[5];
    const float* gb1    = (const float*)d_in[6];
    const float* gW2    = (const float*)d_in[7];
    const float* gb2    = (const float*)d_in[8];
    const float* gw     = (const float*)d_in[9];
    float* out = (float*)d_out;

    const size_t smem = (size_t)SMF * sizeof(float);   // 217,344 bytes
    cudaFuncSetAttribute(nlf_kernel, cudaFuncAttributeMaxDynamicSharedMemorySize, (int)smem);
    nlf_kernel<<<B_N, NT, smem>>>(gk, gK, glogQ, gm0, glogv0, gW1, gb1, gW2, gb2, gw, out);
}

// round 3
// speedup vs baseline: 1.0040x; 1.0040x over previous
#include <cuda_runtime.h>
#include <math.h>

// Problem constants
#define S_N 16
#define B_N 128
#define T_N 200
#define L_N 64
#define R_N 16
#define H_N 256
#define NT  256
#define LP  65            // padded row stride for 64x64 matrices (conflict-free column reads)
#define TRI (L_N*(L_N+1)/2)   // 2080 lower-tri entries

// ---- shared memory layout (floats) ----
#define O_W1  0
#define O_W2  (O_W1 + L_N*H_N)        // 16384
#define O_B1  (O_W2 + H_N*L_N)        // +16384
#define O_B2  (O_B1 + H_N)
#define O_Z   (O_B2 + L_N)
#define O_HID (O_Z + S_N*L_N)
#define O_M   (O_HID + S_N*H_N)
#define O_A   (O_M + S_N*L_N)
#define O_BI  (O_A + L_N*LP)
#define O_JP  (O_BI + L_N*LP)
#define O_KT  (O_JP + L_N*LP)
#define O_WT  (O_KT + L_N*R_N)
#define O_MP  (O_WT + S_N*L_N)
#define O_HF  (O_MP + L_N)
#define O_MF  (O_HF + L_N)
#define O_U   (O_MF + L_N)
#define O_DG  (O_U + L_N)
#define O_QD  (O_DG + L_N)
#define O_J0  (O_QD + L_N)
#define O_M0  (O_J0 + L_N)
#define O_SP  (O_M0 + L_N)
#define SMF   (O_SP + L_N)            // total floats (= 54336 -> 217344 bytes)

// ---- output offsets (tuple flattened in order) ----
#define OFF_ZF 0LL
#define OFF_MFo ((long long)S_N*B_N*T_N*L_N)                  // 26,214,400
#define OFF_MPo (OFF_MFo + (long long)B_N*T_N*L_N)            // +1,638,400
#define OFF_PF  (OFF_MPo + (long long)B_N*T_N*L_N)
#define OFF_PP  (OFF_PF + (long long)B_N*T_N*L_N*L_N)

// map linear index e -> (i,j) with j<=i over the lower triangle
__device__ __forceinline__ void trimap(int e, int &i, int &j) {
    int ii = (int)((sqrtf(8.0f*(float)e + 1.0f) - 1.0f) * 0.5f);
    while ((ii+1)*(ii+2)/2 <= e) ++ii;
    while (ii*(ii+1)/2 > e) --ii;
    i = ii;
    j = e - ii*(ii+1)/2;
}

// In-place Cholesky of lower-triangular-stored A (stride LP).
// One barrier per column (LDL-style rank-1 updates with unscaled columns),
// then one parallel scaling pass. dg[j] = 1/L[j][j] on exit (needed by solver).
__device__ void chol_inplace(float* A, float* dg, int tid) {
    const int warp = tid >> 5, lane = tid & 31;
    #pragma unroll 1
    for (int j = 0; j < L_N - 1; ++j) {
        __syncthreads();
        const float inv = 1.0f / A[j*LP + j];
        #pragma unroll 1
        for (int i = j + 1 + warp; i < L_N; i += NT/32) {
            const float fac = A[i*LP + j] * inv;
            for (int kk = j + 1 + lane; kk <= i; kk += 32)
                A[i*LP + kk] -= fac * A[kk*LP + j];
        }
    }
    __syncthreads();
    if (tid < L_N) dg[tid] = rsqrtf(A[tid*LP + tid]);
    __syncthreads();
    for (int e = tid; e < TRI; e += NT) {
        int i, j; trimap(e, i, j);
        A[i*LP + j] *= dg[j];     // diag becomes sqrt(d_j); dg[j] stays = 1/L[j][j]
    }
    __syncthreads();
}

// X = inv(A) for lower-triangular A (reads lower part only, writes lower part of X).
// Row-sweep forward substitution, all 64 unit-vector RHS in parallel:
// 4 lanes per column split the dot product, shfl-reduced.
__device__ void tri_inverse(const float* A, float* X, const float* dg, int tid) {
    const int c = tid >> 2, r = tid & 3;
    #pragma unroll 1
    for (int i = 0; i < L_N; ++i) {
        __syncthreads();
        float sum = 0.0f;
        for (int j = c + r; j < i; j += 4)
            sum += A[i*LP + j] * X[j*LP + c];
        sum += __shfl_down_sync(0xffffffffu, sum, 1);
        sum += __shfl_down_sync(0xffffffffu, sum, 2);
        if (r == 0 && c <= i)
            X[i*LP + c] = (c == i) ? dg[i] : (-sum * dg[i]);
    }
    __syncthreads();
}

__global__ void __launch_bounds__(NT, 1)
nlf_kernel(const float* __restrict__ gk,  const float* __restrict__ gK,
           const float* __restrict__ glogQ, const float* __restrict__ gm0,
           const float* __restrict__ glogv0, const float* __restrict__ gW1,
           const float* __restrict__ gb1, const float* __restrict__ gW2,
           const float* __restrict__ gb2, const float* __restrict__ gw,
           float* __restrict__ out)
{
    extern __shared__ float sm[];
    const int tid = threadIdx.x;
    const int b   = blockIdx.x;

    // ---- one-time setup: weights + softplus-derived vectors ----
    {
        const float4* g1 = (const float4*)gW1;
        float4* s1 = (float4*)(sm + O_W1);
        for (int i = tid; i < L_N*H_N/4; i += NT) s1[i] = g1[i];
        const float4* g2 = (const float4*)gW2;
        float4* s2 = (float4*)(sm + O_W2);
        for (int i = tid; i < H_N*L_N/4; i += NT) s2[i] = g2[i];
        if (tid < H_N) sm[O_B1 + tid] = gb1[tid];
        if (tid < L_N) {
            sm[O_B2 + tid] = gb2[tid];
            float q = glogQ[tid], v = glogv0[tid];
            float qd = fmaxf(q, 0.f) + log1pf(expf(-fabsf(q)));   // softplus(log_Q)
            float p0 = fmaxf(v, 0.f) + log1pf(expf(-fabsf(v)));   // softplus(log_v0)
            sm[O_QD + tid] = qd;
            sm[O_J0 + tid] = 1.0f / p0;
            sm[O_SP + tid] = sqrtf(p0);
            sm[O_M0 + tid] = gm0[tid];
        }
    }
    __syncthreads();

    float* const sZ  = sm + O_Z;
    float* const sHID= sm + O_HID;
    float* const sM  = sm + O_M;
    float* const sA  = sm + O_A;
    float* const sBI = sm + O_BI;
    float* const sJP = sm + O_JP;
    float* const sKT = sm + O_KT;
    float* const sWT = sm + O_WT;
    float* const sMP = sm + O_MP;
    float* const sHF = sm + O_HF;
    float* const sMF = sm + O_MF;
    float* const sU  = sm + O_U;
    float* const sDG = sm + O_DG;

    #pragma unroll 1
    for (int t = 0; t < T_N; ++t) {
        // ---- stage K_t (64x16) and w_t (16x64) early (prefetch-ish) ----
        {
            const float4* gkt = (const float4*)(gK + ((long long)(b*T_N + t))*L_N*R_N);
            float4* s4 = (float4*)sKT;
            for (int i = tid; i < L_N*R_N/4; i += NT) s4[i] = gkt[i];
            // w[t][s][b][:]: per-sample rows are strided by B*L floats
            const int ss = tid >> 4;            // 16 samples
            const int l4 = (tid & 15) * 4;      // 16 float4 per sample row
            const float4 wv = *(const float4*)(gw + (((long long)t*S_N + ss)*B_N + b)*L_N + l4);
            *(float4*)(sWT + ss*L_N + l4) = wv;
        }
        __syncthreads();

        if (t == 0) {
            if (tid < L_N) {
                sMP[tid] = sm[O_M0 + tid];
                sHF[tid] = sm[O_J0 + tid]*sm[O_M0 + tid] + gk[((long long)(b*T_N))*L_N + tid];
            }
            // P_p_chol[t=0] = diag(sqrt(P0))
            {
                float* po = out + OFF_PP + ((long long)(b*T_N + t))*L_N*L_N;
                for (int e = tid; e < L_N*L_N; e += NT) {
                    int i = e >> 6, j = e & 63;
                    po[e] = (i == j) ? sm[O_SP + i] : 0.0f;
                }
            }
            // J_f = diag(J0) + K0 K0^T (lower only)
            for (int e = tid; e < TRI; e += NT) {
                int i, j; trimap(e, i, j);
                float s = 0.f;
                #pragma unroll
                for (int rr = 0; rr < R_N; rr += 4) {
                    float4 a  = *(const float4*)(sKT + i*R_N + rr);
                    float4 bb = *(const float4*)(sKT + j*R_N + rr);
                    s += a.x*bb.x + a.y*bb.y + a.z*bb.z + a.w*bb.w;
                }
                if (i == j) s += sm[O_J0 + i];
                sA[i*LP + j] = s;
            }
        } else {
            // ---- MLP layer 1: hid = tanh(z @ W1 + b1), one h per thread ----
            {
                const int h = tid;
                float acc[S_N];
                const float bb1 = sm[O_B1 + h];
                #pragma unroll
                for (int s = 0; s < S_N; ++s) acc[s] = bb1;
                #pragma unroll 4
                for (int l = 0; l < L_N; l += 4) {
                    const float w0 = sm[O_W1 + (l+0)*H_N + h];
                    const float w1 = sm[O_W1 + (l+1)*H_N + h];
                    const float w2 = sm[O_W1 + (l+2)*H_N + h];
                    const float w3 = sm[O_W1 + (l+3)*H_N + h];
                    #pragma unroll
                    for (int s = 0; s < S_N; ++s) {
                        float4 z4 = *(const float4*)(sZ + s*L_N + l);
                        acc[s] += z4.x*w0 + z4.y*w1 + z4.z*w2 + z4.w*w3;
                    }
                }
                #pragma unroll
                for (int s = 0; s < S_N; ++s) sHID[s*H_N + h] = tanhf(acc[s]);
            }
            __syncthreads();
            // ---- MLP layer 2: m = hid @ W2 + b2, (4 samples, 1 column) per thread ----
            {
                const int lo = tid & 63;
                const int s0 = (tid >> 6) * 4;
                const float bb2 = sm[O_B2 + lo];
                float a0 = bb2, a1 = bb2, a2 = bb2, a3 = bb2;
                #pragma unroll 4
                for (int h = 0; h < H_N; h += 4) {
                    const float w0 = sm[O_W2 + (h+0)*L_N + lo];
                    const float w1 = sm[O_W2 + (h+1)*L_N + lo];
                    const float w2 = sm[O_W2 + (h+2)*L_N + lo];
                    const float w3 = sm[O_W2 + (h+3)*L_N + lo];
                    float4 h0 = *(const float4*)(sHID + (s0+0)*H_N + h);
                    float4 h1 = *(const float4*)(sHID + (s0+1)*H_N + h);
                    float4 h2 = *(const float4*)(sHID + (s0+2)*H_N + h);
                    float4 h3 = *(const float4*)(sHID + (s0+3)*H_N + h);
                    a0 += h0.x*w0 + h0.y*w1 + h0.z*w2 + h0.w*w3;
                    a1 += h1.x*w0 + h1.y*w1 + h1.z*w2 + h1.w*w3;
                    a2 += h2.x*w0 + h2.y*w1 + h2.z*w2 + h2.w*w3;
                    a3 += h3.x*w0 + h3.y*w1 + h3.z*w2 + h3.w*w3;
                }
                sM[(s0+0)*L_N + lo] = a0;
                sM[(s0+1)*L_N + lo] = a1;
                sM[(s0+2)*L_N + lo] = a2;
                sM[(s0+3)*L_N + lo] = a3;
            }
            __syncthreads();
            // ---- m_p = mean_s m ----
            if (tid < L_N) {
                float s = 0.f;
                #pragma unroll
                for (int ss = 0; ss < S_N; ++ss) s += sM[ss*L_N + tid];
                sMP[tid] = s * (1.0f/S_N);
            }
            __syncthreads();
            // ---- P_p = diag(Q) + Ezz/S - m_p m_p^T (lower only) ----
            for (int e = tid; e < TRI; e += NT) {
                int i, j; trimap(e, i, j);
                float s = 0.f;
                #pragma unroll
                for (int ss = 0; ss < S_N; ++ss) s += sM[ss*L_N + i]*sM[ss*L_N + j];
                float v = s * (1.0f/S_N) - sMP[i]*sMP[j];
                if (i == j) v += sm[O_QD + i];
                sA[i*LP + j] = v;
            }
            chol_inplace(sA, sDG, tid);          // sA = Lp
            // write P_p_chol
            {
                float* po = out + OFF_PP + ((long long)(b*T_N + t))*L_N*L_N;
                for (int e = tid; e < L_N*L_N; e += NT) {
                    int i = e >> 6, j = e & 63;
                    po[e] = (j <= i) ? sA[i*LP + j] : 0.0f;
                }
            }
            tri_inverse(sA, sBI, sDG, tid);      // sBI = Lp^{-1}
            // ---- J_p = BI^T BI (lower + mirror) ----
            for (int e = tid; e < TRI; e += NT) {
                int i, j; trimap(e, i, j);       // i >= j; sum k = i..63
                float s0 = 0.f, s1 = 0.f;
                int kk = i;
                for (; kk + 1 < L_N; kk += 2) {
                    s0 += sBI[(kk+0)*LP + i] * sBI[(kk+0)*LP + j];
                    s1 += sBI[(kk+1)*LP + i] * sBI[(kk+1)*LP + j];
                }
                if (kk < L_N) s0 += sBI[kk*LP + i] * sBI[kk*LP + j];
                const float s = s0 + s1;
                sJP[i*LP + j] = s;
                sJP[j*LP + i] = s;
            }
            __syncthreads();
            // ---- h_f = J_p m_p + k_t ----
            if (tid < L_N) {
                const float* row = sJP + tid*LP;
                float s0=0,s1=0,s2=0,s3=0;
                #pragma unroll
                for (int j = 0; j < L_N; j += 4) {
                    s0 += row[j+0]*sMP[j+0];
                    s1 += row[j+1]*sMP[j+1];
                    s2 += row[j+2]*sMP[j+2];
                    s3 += row[j+3]*sMP[j+3];
                }
                sHF[tid] = (s0+s1)+(s2+s3) + gk[((long long)(b*T_N + t))*L_N + tid];
            }
            __syncthreads();
            // ---- J_f = J_p + K_t K_t^T (lower only) ----
            for (int e = tid; e < TRI; e += NT) {
                int i, j; trimap(e, i, j);
                float s = 0.f;
                #pragma unroll
                for (int rr = 0; rr < R_N; rr += 4) {
                    float4 a  = *(const float4*)(sKT + i*R_N + rr);
                    float4 bb = *(const float4*)(sKT + j*R_N + rr);
                    s += a.x*bb.x + a.y*bb.y + a.z*bb.z + a.w*bb.w;
                }
                sA[i*LP + j] = sJP[i*LP + j] + s;
            }
        }

        // ================= common tail =================
        chol_inplace(sA, sDG, tid);        // sA = Lf (internal leading barrier orders the build)
        tri_inverse(sA, sBI, sDG, tid);    // sBI = Lf^{-1}

        // m_f = Lf^{-T} (Lf^{-1} h_f)
        if (tid < L_N) {
            const int i = tid;
            float s0 = 0.f, s1 = 0.f;
            int j = 0;
            for (; j + 1 <= i; j += 2) {
                s0 += sBI[i*LP + j]   * sHF[j];
                s1 += sBI[i*LP + j+1] * sHF[j+1];
            }
            if (j <= i) s0 += sBI[i*LP + j] * sHF[j];
            sU[i] = s0 + s1;
        }
        __syncthreads();
        if (tid < L_N) {
            const int i = tid;
            float s0 = 0.f, s1 = 0.f;
            int kk = i;
            for (; kk + 1 < L_N; kk += 2) {
                s0 += sBI[(kk+0)*LP + i] * sU[kk+0];
                s1 += sBI[(kk+1)*LP + i] * sU[kk+1];
            }
            if (kk < L_N) s0 += sBI[kk*LP + i] * sU[kk];
            sMF[i] = s0 + s1;
            out[OFF_MPo + ((long long)(b*T_N + t))*L_N + i] = sMP[i];
        }
        __syncthreads();
        if (tid < L_N)
            out[OFF_MFo + ((long long)(b*T_N + t))*L_N + tid] = sMF[tid];
        // P_f_chol = (Lf^{-1})^T  (upper triangular, zeros below)
        {
            float* po = out + OFF_PF + ((long long)(b*T_N + t))*L_N*L_N;
            for (int e = tid; e < L_N*L_N; e += NT) {
                int i = e >> 6, j = e & 63;
                po[e] = (j >= i) ? sBI[j*LP + i] : 0.0f;
            }
        }
        // z_f[s] = m_f + Pf_chol @ w_t[s]  (sum over j >= i of BI[j][i] * w[s][j])
        {
            const int i  = tid & 63;
            const int s0 = (tid >> 6) * 4;
            float z0 = sMF[i], z1 = z0, z2 = z0, z3 = z0;
            for (int j = i; j < L_N; ++j) {
                const float bv = sBI[j*LP + i];
                z0 += bv * sWT[(s0+0)*L_N + j];
                z1 += bv * sWT[(s0+1)*L_N + j];
                z2 += bv * sWT[(s0+2)*L_N + j];
                z3 += bv * sWT[(s0+3)*L_N + j];
            }
            sZ[(s0+0)*L_N + i] = z0;
            sZ[(s0+1)*L_N + i] = z1;
            sZ[(s0+2)*L_N + i] = z2;
            sZ[(s0+3)*L_N + i] = z3;
            out[((((long long)(s0+0))*B_N + b)*T_N + t)*L_N + i] = z0;
            out[((((long long)(s0+1))*B_N + b)*T_N + t)*L_N + i] = z1;
            out[((((long long)(s0+2))*B_N + b)*T_N + t)*L_N + i] = z2;
            out[((((long long)(s0+3))*B_N + b)*T_N + t)*L_N + i] = z3;
        }
        __syncthreads();   // sZ ready for next step's MLP; staging buffers free
    }
}

extern "C" void kernel_launch(void* const* d_in, const int* in_sizes, int n_in,
                              void* d_out, int out_size) {
    const float* gk     = (const float*)d_in[0];
    const float* gK     = (const float*)d_in[1];
    const float* glogQ  = (const float*)d_in[2];
    const float* gm0    = (const float*)d_in[3];
    const float* glogv0 = (const float*)d_in[4];
    const float* gW1    = (const float*)d_in[5];
    const float* gb1    = (const float*)d_in[6];
    const float* gW2    = (const float*)d_in[7];
    const float* gb2    = (const float*)d_in[8];
    const float* gw     = (const float*)d_in[9];
    float* out = (float*)d_out;

    const size_t smem = (size_t)SMF * sizeof(float);   // 217,344 bytes
    cudaFuncSetAttribute(nlf_kernel, cudaFuncAttributeMaxDynamicSharedMemorySize, (int)smem);
    nlf_kernel<<<B_N, NT, smem>>>(gk, gK, glogQ, gm0, glogv0, gW1, gb1, gW2, gb2, gw, out);
}